// round 5
// baseline (speedup 1.0000x reference)
#include <cuda_runtime.h>
#include <cstdint>
#include <cstddef>

#define B_ 1024
#define G_ 256
#define K_ 256
#define E_ 64
#define BETA_F 0.05f

// ---------------- scratch (__device__ globals: no runtime allocation) ----------
__device__ float gM [K_*E_*E_];   // 4 MB : M_k = W_k^T W_k
__device__ float gS6[K_*E_*E_];   // 4 MB : sum_{j=0..5} A^j
__device__ float gR [K_*E_*E_];   // 4 MB : 2b*S5 - b^2*S5*M*S5
__device__ float gV [K_*E_];      // 64KB : v_k = mu_k W_k
__device__ float gMunorm[K_];
__device__ float gScore[B_*K_];   // 1 MB
__device__ int   gKmax[B_];

// ---------------- K1: per-k  M, v, ||mu_k||^2 ----------------------------------
__global__ __launch_bounds__(256) void k1_prep(const float* __restrict__ mu,
                                               const float* __restrict__ w)
{
    int k = blockIdx.x;
    int t = threadIdx.x;
    __shared__ float Ws[64*64];   // [g][e] chunk of W_k
    __shared__ float mus[64];
    __shared__ float red[64];
    float acc[16];
#pragma unroll
    for (int i = 0; i < 16; i++) acc[i] = 0.f;
    float vacc = 0.f, mn = 0.f;
    const float* wk = w + (size_t)k * G_ * E_;
    for (int gc = 0; gc < G_; gc += 64) {
        const float* src = wk + (size_t)gc * E_;   // contiguous 4096 floats
        for (int idx = t; idx < 4096; idx += 256) Ws[idx] = src[idx];
        if (t < 64) mus[t] = mu[(size_t)(gc + t) * K_ + k];
        __syncthreads();
#pragma unroll
        for (int r = 0; r < 16; r++) {
            int idx = t + (r << 8);
            int e = idx >> 6, f = idx & 63;
            float a = 0.f;
#pragma unroll 16
            for (int g = 0; g < 64; g++) a += Ws[g*64 + e] * Ws[g*64 + f];
            acc[r] += a;
        }
        if (t < 64) {
            float va = 0.f;
#pragma unroll 16
            for (int g = 0; g < 64; g++) va += mus[g] * Ws[g*64 + t];
            vacc += va;
            mn += mus[t] * mus[t];
        }
        __syncthreads();
    }
    float* Mk = gM + (size_t)k * 4096;
#pragma unroll
    for (int r = 0; r < 16; r++) Mk[t + (r << 8)] = acc[r];
    if (t < 64) { gV[k*E_ + t] = vacc; red[t] = mn; }
    __syncthreads();
    if (t == 0) { float s = 0.f; for (int i = 0; i < 64; i++) s += red[i]; gMunorm[k] = s; }
}

// ---------------- K2: per-k  S6 and R ------------------------------------------
// S_{t+1} = I + A*S_t, A = (1-b)I - b*M.  S_1 = I; after 4 iters Ss = S5.
// S6 = I + (1-b)S5 - b*(M*S5).  R = 2b*S5 - b^2*(M*S5)*S5   (M,S commute, all sym.)
__global__ __launch_bounds__(256) void k2_poly()
{
    int k = blockIdx.x;
    int t = threadIdx.x;
    __shared__ float Ms[64*64];
    __shared__ float Ss[64*64];
    const float* Mk = gM + (size_t)k * 4096;
    for (int idx = t; idx < 4096; idx += 256) {
        Ms[idx] = Mk[idx];
        Ss[idx] = ((idx >> 6) == (idx & 63)) ? 1.f : 0.f;
    }
    __syncthreads();
    for (int it = 0; it < 4; it++) {
        float val[16];
#pragma unroll
        for (int r = 0; r < 16; r++) {
            int idx = t + (r << 8);
            int e = idx >> 6, f = idx & 63;
            float a = 0.f;
#pragma unroll 16
            for (int g = 0; g < 64; g++) a += Ms[e*64 + g] * Ss[g*64 + f];
            float v = (1.f - BETA_F) * Ss[idx] - BETA_F * a;
            if (e == f) v += 1.f;
            val[r] = v;
        }
        __syncthreads();
#pragma unroll
        for (int r = 0; r < 16; r++) Ss[t + (r << 8)] = val[r];
        __syncthreads();
    }
    // Ss = S5. Compute MS5 (into regs), S6 -> gmem, then overwrite Ms with MS5.
    float ms5[16];
#pragma unroll
    for (int r = 0; r < 16; r++) {
        int idx = t + (r << 8);
        int e = idx >> 6, f = idx & 63;
        float a = 0.f;
#pragma unroll 16
        for (int g = 0; g < 64; g++) a += Ms[e*64 + g] * Ss[g*64 + f];
        ms5[r] = a;
        float s6 = (1.f - BETA_F) * Ss[idx] - BETA_F * a;
        if (e == f) s6 += 1.f;
        gS6[(size_t)k*4096 + idx] = s6;
    }
    __syncthreads();
#pragma unroll
    for (int r = 0; r < 16; r++) Ms[t + (r << 8)] = ms5[r];
    __syncthreads();
#pragma unroll
    for (int r = 0; r < 16; r++) {
        int idx = t + (r << 8);
        int e = idx >> 6, f = idx & 63;
        float q = 0.f;
#pragma unroll 16
        for (int g = 0; g < 64; g++) q += Ms[e*64 + g] * Ss[g*64 + f];
        gR[(size_t)k*4096 + idx] = 2.f*BETA_F*Ss[idx] - BETA_F*BETA_F*q;
    }
}

// ---------------- K3: the big one: U = (X - mu_k) W_k, score = 2d + uRu - ||mu||^2
// grid (16, 256): 64-row b-tile x one k. 256 thr, 4x4 micro-tiles.
__global__ __launch_bounds__(256) void k3_score(const float* __restrict__ X,
                                                const float* __restrict__ mu,
                                                const float* __restrict__ w)
{
    const int k  = blockIdx.y;
    const int b0 = blockIdx.x * 64;
    const int t  = threadIdx.x;
    const int tx = t & 15;   // e-group (e = tx*4..tx*4+3)
    const int ty = t >> 4;   // b-group (b = ty*4..ty*4+3)

    __shared__ float sAB[32*68 + 32*64];  // XsT[32][68] | Ws[32][64]; reused as Rs[64][64]
    __shared__ float UsT[64*68];          // [f][b], padded
    __shared__ float mus[32];
    __shared__ float qpart[64];

    float* XsT = sAB;            // stride 68
    float* Ws  = sAB + 32*68;    // stride 64
    float* Rs  = sAB;            // 4096 <= 4224 floats

    float uacc[4][4];
#pragma unroll
    for (int i = 0; i < 4; i++)
#pragma unroll
        for (int l = 0; l < 4; l++) uacc[i][l] = 0.f;
    float dacc = 0.f;

    for (int gc = 0; gc < G_; gc += 32) {
        for (int idx = t; idx < 2048; idx += 256) {
            int i = idx >> 5, j = idx & 31;
            XsT[j*68 + i] = X[(size_t)(b0 + i) * G_ + gc + j];
        }
        {
            const float* wsrc = w + ((size_t)k * G_ + gc) * E_;   // contiguous 2048
            for (int idx = t; idx < 2048; idx += 256) Ws[idx] = wsrc[idx];
        }
        if (t < 32) mus[t] = mu[(size_t)(gc + t) * K_ + k];
        __syncthreads();
#pragma unroll
        for (int j = 0; j < 32; j++) {
            float4 a  = *(const float4*)&XsT[j*68 + ty*4];
            float4 wv = *(const float4*)&Ws [j*64 + tx*4];
            uacc[0][0] += a.x*wv.x; uacc[0][1] += a.x*wv.y; uacc[0][2] += a.x*wv.z; uacc[0][3] += a.x*wv.w;
            uacc[1][0] += a.y*wv.x; uacc[1][1] += a.y*wv.y; uacc[1][2] += a.y*wv.z; uacc[1][3] += a.y*wv.w;
            uacc[2][0] += a.z*wv.x; uacc[2][1] += a.z*wv.y; uacc[2][2] += a.z*wv.z; uacc[2][3] += a.z*wv.w;
            uacc[3][0] += a.w*wv.x; uacc[3][1] += a.w*wv.y; uacc[3][2] += a.w*wv.z; uacc[3][3] += a.w*wv.w;
        }
        if (t < 64) {   // d_b = x_b . mu_k partial
            float dd = 0.f;
#pragma unroll
            for (int j = 0; j < 32; j++) dd += XsT[j*68 + t] * mus[j];
            dacc += dd;
        }
        __syncthreads();
    }

    // u = Xw - v
    {
        const float4 v4 = *(const float4*)&gV[k*E_ + tx*4];
#pragma unroll
        for (int i = 0; i < 4; i++) {
            uacc[i][0] -= v4.x; uacc[i][1] -= v4.y; uacc[i][2] -= v4.z; uacc[i][3] -= v4.w;
        }
    }
    // stage u transposed for the quadform GEMM; load R over the (now-dead) GEMM tiles
#pragma unroll
    for (int i = 0; i < 4; i++)
#pragma unroll
        for (int l = 0; l < 4; l++)
            UsT[(tx*4 + l)*68 + ty*4 + i] = uacc[i][l];
    {
        const float* Rk = gR + (size_t)k * 4096;
        for (int idx = t; idx < 4096; idx += 256) Rs[idx] = Rk[idx];
    }
    __syncthreads();

    // T = U * R  (register accumulators), then s_b = sum_e T[b][e]*u[b][e]
    float tacc[4][4];
#pragma unroll
    for (int i = 0; i < 4; i++)
#pragma unroll
        for (int l = 0; l < 4; l++) tacc[i][l] = 0.f;
#pragma unroll
    for (int f = 0; f < 64; f++) {
        float4 uu = *(const float4*)&UsT[f*68 + ty*4];
        float4 rr = *(const float4*)&Rs [f*64 + tx*4];
        tacc[0][0] += uu.x*rr.x; tacc[0][1] += uu.x*rr.y; tacc[0][2] += uu.x*rr.z; tacc[0][3] += uu.x*rr.w;
        tacc[1][0] += uu.y*rr.x; tacc[1][1] += uu.y*rr.y; tacc[1][2] += uu.y*rr.z; tacc[1][3] += uu.y*rr.w;
        tacc[2][0] += uu.z*rr.x; tacc[2][1] += uu.z*rr.y; tacc[2][2] += uu.z*rr.z; tacc[2][3] += uu.z*rr.w;
        tacc[3][0] += uu.w*rr.x; tacc[3][1] += uu.w*rr.y; tacc[3][2] += uu.w*rr.z; tacc[3][3] += uu.w*rr.w;
    }
    float p[4];
#pragma unroll
    for (int i = 0; i < 4; i++) {
        p[i] = tacc[i][0]*uacc[i][0] + tacc[i][1]*uacc[i][1]
             + tacc[i][2]*uacc[i][2] + tacc[i][3]*uacc[i][3];
#pragma unroll
        for (int ofs = 8; ofs > 0; ofs >>= 1)
            p[i] += __shfl_down_sync(0xffffffffu, p[i], ofs, 16);
    }
    if (tx == 0) {
#pragma unroll
        for (int i = 0; i < 4; i++) qpart[ty*4 + i] = p[i];
    }
    __syncthreads();
    if (t < 64) {
        // maximize  -||dx||^2  <=>  maximize  2*d + uRu - ||mu_k||^2
        gScore[(size_t)(b0 + t) * K_ + k] = 2.f*dacc + qpart[t] - gMunorm[k];
    }
}

// ---------------- K4: argmax over k (first-max tie-break, like jnp.argmax) -----
__global__ __launch_bounds__(256) void k4_argmax()
{
    int b = blockIdx.x;
    int t = threadIdx.x;
    __shared__ float sv[256];
    __shared__ int   si[256];
    sv[t] = gScore[(size_t)b * K_ + t];
    si[t] = t;
    __syncthreads();
    for (int s = 128; s > 0; s >>= 1) {
        if (t < s) {
            float v2 = sv[t + s]; int i2 = si[t + s];
            if (v2 > sv[t] || (v2 == sv[t] && i2 < si[t])) { sv[t] = v2; si[t] = i2; }
        }
        __syncthreads();
    }
    if (t == 0) gKmax[b] = si[0];
}

// ---------------- K5: decode winner: y = beta*u*S6*W^T + mu_k ------------------
__global__ __launch_bounds__(256) void k5_decode(const float* __restrict__ X,
                                                 const float* __restrict__ mu,
                                                 const float* __restrict__ w,
                                                 float* __restrict__ y)
{
    int b = blockIdx.x;
    int t = threadIdx.x;
    __shared__ float upart[4][64];
    __shared__ float us[64];
    __shared__ float z6[64];
    int k = gKmax[b];
    const float* wk = w + (size_t)k * G_ * E_;

    {   // u[e] = sum_g X[b][g]*wk[g][e] - v[k][e], 4-way g split
        int e = t & 63, gq = t >> 6;
        float a = 0.f;
        const float* xb = X + (size_t)b * G_;
#pragma unroll 16
        for (int g = gq*64; g < gq*64 + 64; g++) a += xb[g] * wk[(size_t)g*E_ + e];
        upart[gq][e] = a;
    }
    __syncthreads();
    if (t < 64) us[t] = upart[0][t] + upart[1][t] + upart[2][t] + upart[3][t] - gV[k*E_ + t];
    __syncthreads();
    if (t < 64) {
        const float* S6k = gS6 + (size_t)k * 4096;
        float a = 0.f;
#pragma unroll 16
        for (int f = 0; f < 64; f++) a += us[f] * S6k[f*64 + t];
        z6[t] = BETA_F * a;
    }
    __syncthreads();
    {
        int g = t;
        float a = 0.f;
        const float* wg = wk + (size_t)g * E_;
#pragma unroll
        for (int e = 0; e < 64; e++) a += z6[e] * wg[e];
        y[(size_t)b * G_ + g] = a + mu[(size_t)g * K_ + k];
    }
}

// ---------------- launch --------------------------------------------------------
extern "C" void kernel_launch(void* const* d_in, const int* in_sizes, int n_in,
                              void* d_out, int out_size)
{
    const float* X  = (const float*)d_in[0];   // images (B,G)
    const float* mu = (const float*)d_in[1];   // (G,K)
    const float* w  = (const float*)d_in[2];   // (K,G,E)
    float* y = (float*)d_out;                  // (B,G)

    k1_prep<<<K_, 256>>>(mu, w);
    k2_poly<<<K_, 256>>>();
    dim3 g3(B_/64, K_);
    k3_score<<<g3, 256>>>(X, mu, w);
    k4_argmax<<<B_, 256>>>();
    k5_decode<<<B_, 256>>>(X, mu, w, y);
}